// round 5
// baseline (speedup 1.0000x reference)
#include <cuda_runtime.h>
#include <math.h>

#define NQ 12
#define DIM 4096
#define QUADS 1024
#define NL 4
#define NC 10
#define BATCH 512
#define TPB 256
#define BN_EPS 1e-5f
#define NSWEEP (NL * NQ / 2)   // 24

typedef unsigned long long u64;

// Scratch for softmax probs (B x NC). __device__ global: allocation-free.
__device__ float g_probs[BATCH * NC];

// storage swizzle: amplitude i lives at slot i ^ (i>>4)  (bijective, XOR-linear)
__device__ __forceinline__ int sw(int i) { return i ^ (i >> 4); }

// ---- packed f32x2 helpers ----
__device__ __forceinline__ u64 swap64(u64 v) {  // (x,y) -> (y,x)
    u64 r;
    asm("{\n\t.reg .b32 x, y;\n\tmov.b64 {x, y}, %1;\n\tmov.b64 %0, {y, x};\n\t}"
        : "=l"(r) : "l"(v));
    return r;
}
__device__ __forceinline__ u64 fma2(u64 a, u64 b, u64 c) {
    u64 d; asm("fma.rn.f32x2 %0, %1, %2, %3;" : "=l"(d) : "l"(a), "l"(b), "l"(c));
    return d;
}
__device__ __forceinline__ u64 mul2(u64 a, u64 b) {
    u64 d; asm("mul.rn.f32x2 %0, %1, %2;" : "=l"(d) : "l"(a), "l"(b));
    return d;
}
__device__ __forceinline__ u64 pack2(float lo, float hi) {
    u64 d; asm("mov.b64 %0, {%1, %2};" : "=l"(d) : "f"(lo), "f"(hi));
    return d;
}

// packed SU(2) gate: U = [[a, b], [-b*, a*]], 6 broadcast/sign-prepped f32x2 consts
struct PG { u64 axx, ayn, ayc, bxx, bxn, byn; };

__device__ __forceinline__ PG mkpg(float2 al, float2 be) {
    PG g;
    g.axx = pack2(al.x, al.x);
    g.ayn = pack2(-al.y, al.y);
    g.ayc = pack2(al.y, -al.y);
    g.bxx = pack2(be.x, be.x);
    g.bxn = pack2(-be.x, -be.x);
    g.byn = pack2(-be.y, be.y);
    return g;
}

// (a,b) <- U (a,b), amplitudes packed as (re,im) f32x2
__device__ __forceinline__ void pgate(const PG& g, u64& a, u64& b) {
    const u64 as = swap64(a), bs = swap64(b);
    u64 t = mul2(g.byn, bs);          // na = alpha*a + beta*b
    t = fma2(g.bxx, b, t);
    t = fma2(g.ayn, as, t);
    t = fma2(g.axx, a, t);
    u64 u = mul2(g.ayc, bs);          // nb = -conj(beta)*a + conj(alpha)*b
    u = fma2(g.axx, b, u);
    u = fma2(g.byn, as, u);
    u = fma2(g.bxn, a, u);
    a = t; b = u;
}

__global__ __launch_bounds__(TPB, 4) void vqc_kernel(const float* __restrict__ x,
                                                     const float* __restrict__ w,
                                                     const float* __restrict__ bias) {
    __shared__ float2 st[DIM];                 // state, swizzled slots
    __shared__ float2 s_g[NL * NQ][2];         // fused RY*Rot gate: (U00, U01)
    __shared__ int    s_Mp[NL + 1][NQ];        // rows of M^l, l = 0..4
    __shared__ int    s_Mip[NL][NQ];           // rows of M^{-l}, l = 0..3
    __shared__ int    s_sp[NSWEEP][12];        // per sweep: v1, v2, bas[0..9]
    __shared__ float  s_ez[NC];

    const int b = blockIdx.x;
    const int tid = threadIdx.x;

    // ---- phase A: init state, GF(2) ring matrices, fused gate matrices ----
    for (int i = tid; i < DIM; i += TPB)
        st[i] = make_float2(i == 0 ? 1.0f : 0.0f, 0.0f);   // sw(0)==0
    if (tid < NC) s_ez[tid] = 0.0f;

    if (tid == 0) {
        // ring map M (amplitude perm C|i> = |M i>), built in application order
        int M[NQ], Mi[NQ];
        for (int r = 0; r < NQ; r++) { M[r] = 1 << r; Mi[r] = 1 << r; }
        for (int q = 0; q < NQ; q++) {           // CNOT(q, q+1), q ascending
            int pc = NQ - 1 - q, pt = NQ - 1 - ((q + 1) % NQ);
            M[pt] ^= M[pc];
        }
        for (int q = NQ - 1; q >= 0; q--) {      // inverse: reversed order
            int pc = NQ - 1 - q, pt = NQ - 1 - ((q + 1) % NQ);
            Mi[pt] ^= Mi[pc];
        }
        // powers M^l and M^{-l}
        int P[NQ], Pi[NQ];
        for (int r = 0; r < NQ; r++) { P[r] = 1 << r; Pi[r] = 1 << r; }
        for (int l = 0; l <= NL; l++) {
            for (int r = 0; r < NQ; r++) s_Mp[l][r] = P[r];
            if (l < NL) for (int r = 0; r < NQ; r++) s_Mip[l][r] = Pi[r];
            int Pn[NQ], Pin[NQ];
            for (int r = 0; r < NQ; r++) {
                int acc = 0, acci = 0;
                for (int s = 0; s < NQ; s++) {
                    if ((M[r]  >> s) & 1) acc  ^= P[s];
                    if ((Mi[r] >> s) & 1) acci ^= Pi[s];
                }
                Pn[r] = acc; Pin[r] = acci;
            }
            for (int r = 0; r < NQ; r++) { P[r] = Pn[r]; Pi[r] = Pin[r]; }
        }
    }

    if (tid < NL * NQ) {   // fused gate U = Rot(w) @ RY(x); store alpha=U00, beta=U01
        const int l = tid / NQ, q = tid % NQ;
        const float xh = 0.5f * x[b * NQ + q];
        float sy, cy; sincosf(xh, &sy, &cy);
        const float phi = w[(l * NQ + q) * 3 + 0];
        const float th  = w[(l * NQ + q) * 3 + 1];
        const float om  = w[(l * NQ + q) * 3 + 2];
        float stt, ct; sincosf(0.5f * th, &stt, &ct);
        const float a1 = -0.5f * (phi + om);
        const float a2 =  0.5f * (phi - om);
        float s1, c1, s2, c2;
        sincosf(a1, &s1, &c1);
        sincosf(a2, &s2, &c2);
        const float R00r =  c1 * ct, R00i =  s1 * ct;
        const float R01r = -c2 * stt, R01i = -s2 * stt;
        s_g[tid][0] = make_float2( R00r * cy + R01r * sy,  R00i * cy + R01i * sy);
        s_g[tid][1] = make_float2(-R00r * sy + R01r * cy, -R00i * sy + R01i * cy);
    }
    __syncthreads();

    // ---- phase B: per-sweep params (masks + null-space basis) ----
    if (tid < NSWEEP) {
        const int l = tid / 6, k = tid % 6;
        const int pa = NQ - 1 - 2 * k;           // bit of qubit 2k
        const int pb = NQ - 1 - (2 * k + 1);     // bit of qubit 2k+1
        int v1 = 0, v2 = 0;                      // columns of M^{-l}
        for (int r = 0; r < NQ; r++) {
            v1 |= ((s_Mip[l][r] >> pa) & 1) << r;
            v2 |= ((s_Mip[l][r] >> pb) & 1) << r;
        }
        int D1 = s_Mp[l][pa], D2 = s_Mp[l][pb];  // duals: rows of M^l
        const int p1 = __ffs(D1) - 1;
        if ((D2 >> p1) & 1) D2 ^= D1;
        const int p2 = __ffs(D2) - 1;
        if ((D1 >> p2) & 1) D1 ^= D2;
        s_sp[tid][0] = v1;
        s_sp[tid][1] = v2;
        int freeb = 0xFFF & ~((1 << p1) | (1 << p2));
        for (int jj = 0; jj < 10; jj++) {
            const int j = __ffs(freeb) - 1; freeb &= freeb - 1;
            s_sp[tid][2 + jj] = (1 << j) ^ (((D1 >> j) & 1) << p1)
                                         ^ (((D2 >> j) & 1) << p2);
        }
    }
    __syncthreads();

    u64* st64 = reinterpret_cast<u64*>(st);

    // ---- phase C: 24 two-qubit sweeps (CNOT rings folded into masks) ----
    for (int swp = 0; swp < NSWEEP; swp++) {
        const int l = swp / 6, k = swp % 6;
        // swizzled pair/quad offsets (sw is XOR-linear)
        const int sv1  = sw(s_sp[swp][0]);
        const int sv2  = sw(s_sp[swp][1]);
        const int sv12 = sv1 ^ sv2;
        const int sb8  = sw(s_sp[swp][10]);
        const int sb9  = sw(s_sp[swp][11]);

        // swizzled base slot for this thread
        int i0b = 0;
#pragma unroll
        for (int jj = 0; jj < 8; jj++)
            i0b ^= ((tid >> jj) & 1) ? s_sp[swp][2 + jj] : 0;
        const int base = sw(i0b);

        const PG Ga = mkpg(s_g[l * NQ + 2 * k][0],     s_g[l * NQ + 2 * k][1]);
        const PG Gb = mkpg(s_g[l * NQ + 2 * k + 1][0], s_g[l * NQ + 2 * k + 1][1]);

#pragma unroll 2
        for (int u = 0; u < QUADS / TPB; u++) {
            const int j00 = base ^ ((u & 1) ? sb8 : 0) ^ ((u & 2) ? sb9 : 0);
            const int j01 = j00 ^ sv2;
            const int j10 = j00 ^ sv1;
            const int j11 = j00 ^ sv12;
            u64 s00 = st64[j00], s01 = st64[j01], s10 = st64[j10], s11 = st64[j11];
            pgate(Gb, s00, s01);   // U_b on qubit 2k+1
            pgate(Gb, s10, s11);
            pgate(Ga, s00, s10);   // U_a on qubit 2k
            pgate(Ga, s01, s11);
            st64[j00] = s00; st64[j01] = s01; st64[j10] = s10; st64[j11] = s11;
        }
        __syncthreads();
    }

    // ---- measurement: <Z_c>, final C^4 folded in; iterate slots directly ----
    // parity(i & d) with i = sw^{-1}(s)  ==  parity(s & d~), d~ = (d^d<<4^d<<8)&0xFFF
    int dz[NC];
#pragma unroll
    for (int c = 0; c < NC; c++) {
        const int d = s_Mp[NL][NQ - 1 - c];
        dz[c] = (d ^ (d << 4) ^ (d << 8)) & 0xFFF;
    }

    float ez[NC];
#pragma unroll
    for (int c = 0; c < NC; c++) ez[c] = 0.0f;
    for (int s = tid; s < DIM; s += TPB) {
        const float2 a = st[s];
        const float p = a.x * a.x + a.y * a.y;
#pragma unroll
        for (int c = 0; c < NC; c++)
            ez[c] += (__popc(s & dz[c]) & 1) ? -p : p;
    }
#pragma unroll
    for (int c = 0; c < NC; c++) {
        float v = ez[c];
        for (int o = 16; o > 0; o >>= 1) v += __shfl_down_sync(0xffffffffu, v, o);
        if ((tid & 31) == 0) atomicAdd(&s_ez[c], v);
    }
    __syncthreads();

    // ---- softmax(expz + bias) -> g_probs ----
    if (tid == 0) {
        float z[NC];
        float m = -1e30f;
#pragma unroll
        for (int c = 0; c < NC; c++) {
            z[c] = s_ez[c] + bias[c];
            m = fmaxf(m, z[c]);
        }
        float sum = 0.0f;
#pragma unroll
        for (int c = 0; c < NC; c++) {
            z[c] = expf(z[c] - m);
            sum += z[c];
        }
        const float inv = 1.0f / sum;
#pragma unroll
        for (int c = 0; c < NC; c++) g_probs[b * NC + c] = z[c] * inv;
    }
}

// BatchNorm1d over the batch, per class. 10 blocks x 512 threads.
__global__ __launch_bounds__(BATCH) void bn_kernel(const float* __restrict__ gamma,
                                                   const float* __restrict__ beta,
                                                   float* __restrict__ out) {
    const int c = blockIdx.x;
    const int t = threadIdx.x;  // = batch index

    const float p = g_probs[t * NC + c];

    __shared__ float ssum[BATCH / 32];
    __shared__ float ssq[BATCH / 32];
    float s = p, q = p * p;
    for (int o = 16; o > 0; o >>= 1) {
        s += __shfl_down_sync(0xffffffffu, s, o);
        q += __shfl_down_sync(0xffffffffu, q, o);
    }
    if ((t & 31) == 0) {
        ssum[t >> 5] = s;
        ssq[t >> 5] = q;
    }
    __syncthreads();

    __shared__ float smu, srstd;
    if (t == 0) {
        float S = 0.0f, Q = 0.0f;
#pragma unroll
        for (int i = 0; i < BATCH / 32; i++) { S += ssum[i]; Q += ssq[i]; }
        const float mu = S / (float)BATCH;
        const float var = Q / (float)BATCH - mu * mu;
        smu = mu;
        srstd = rsqrtf(var + BN_EPS);
    }
    __syncthreads();

    out[t * NC + c] = (p - smu) * srstd * gamma[c] + beta[c];
}

extern "C" void kernel_launch(void* const* d_in, const int* in_sizes, int n_in,
                              void* d_out, int out_size) {
    const float* x      = (const float*)d_in[0];  // (512, 12)
    const float* wts    = (const float*)d_in[1];  // (4, 12, 3)
    const float* bias   = (const float*)d_in[2];  // (10,)
    const float* gamma  = (const float*)d_in[3];  // (10,)
    const float* beta   = (const float*)d_in[4];  // (10,)
    float* out = (float*)d_out;                   // (512, 10)

    vqc_kernel<<<BATCH, TPB>>>(x, wts, bias);
    bn_kernel<<<NC, BATCH>>>(gamma, beta, out);
}

// round 6
// speedup vs baseline: 1.0751x; 1.0751x over previous
#include <cuda_runtime.h>
#include <math.h>

#define NQ 12
#define DIM 4096
#define QUADS 1024
#define NL 4
#define NC 10
#define BATCH 512
#define TPB 256
#define BN_EPS 1e-5f
#define NSWEEP (NL * NQ / 2)   // 24

typedef unsigned long long u64;

// Scratch for softmax probs (B x NC). __device__ global: allocation-free.
__device__ float g_probs[BATCH * NC];

// storage swizzle: amplitude i lives at slot i ^ (i>>4)  (bijective, XOR-linear)
__device__ __forceinline__ int sw(int i) { return i ^ (i >> 4); }

// ---- packed f32x2 helpers ----
__device__ __forceinline__ u64 swap64(u64 v) {  // (x,y) -> (y,x)
    u64 r;
    asm("{\n\t.reg .b32 x, y;\n\tmov.b64 {x, y}, %1;\n\tmov.b64 %0, {y, x};\n\t}"
        : "=l"(r) : "l"(v));
    return r;
}
__device__ __forceinline__ u64 fma2(u64 a, u64 b, u64 c) {
    u64 d; asm("fma.rn.f32x2 %0, %1, %2, %3;" : "=l"(d) : "l"(a), "l"(b), "l"(c));
    return d;
}
__device__ __forceinline__ u64 mul2(u64 a, u64 b) {
    u64 d; asm("mul.rn.f32x2 %0, %1, %2;" : "=l"(d) : "l"(a), "l"(b));
    return d;
}
__device__ __forceinline__ u64 pack2(float lo, float hi) {
    u64 d; asm("mov.b64 %0, {%1, %2};" : "=l"(d) : "f"(lo), "f"(hi));
    return d;
}

// packed SU(2) gate: U = [[a, b], [-b*, a*]], 6 broadcast/sign-prepped f32x2 consts
struct PG { u64 axx, ayn, ayc, bxx, bxn, byn; };

__device__ __forceinline__ PG mkpg(float2 al, float2 be) {
    PG g;
    g.axx = pack2(al.x, al.x);
    g.ayn = pack2(-al.y, al.y);
    g.ayc = pack2(al.y, -al.y);
    g.bxx = pack2(be.x, be.x);
    g.bxn = pack2(-be.x, -be.x);
    g.byn = pack2(-be.y, be.y);
    return g;
}

// (a,b) <- U (a,b), amplitudes packed as (re,im) f32x2
__device__ __forceinline__ void pgate(const PG& g, u64& a, u64& b) {
    const u64 as = swap64(a), bs = swap64(b);
    u64 t = mul2(g.byn, bs);          // na = alpha*a + beta*b
    t = fma2(g.bxx, b, t);
    t = fma2(g.ayn, as, t);
    t = fma2(g.axx, a, t);
    u64 u = mul2(g.ayc, bs);          // nb = -conj(beta)*a + conj(alpha)*b
    u = fma2(g.axx, b, u);
    u = fma2(g.byn, as, u);
    u = fma2(g.bxn, a, u);
    a = t; b = u;
}

__global__ __launch_bounds__(TPB, 4) void vqc_kernel(const float* __restrict__ x,
                                                     const float* __restrict__ w,
                                                     const float* __restrict__ bias) {
    __shared__ float2 st[DIM];                 // state, swizzled slots
    __shared__ float2 s_g[NL * NQ][2];         // fused RY*Rot gate: (U00, U01)
    __shared__ int    s_Mp[NL + 1][NQ];        // rows of M^l, l = 0..4
    __shared__ int    s_Mip[NL][NQ];           // rows of M^{-l}, l = 0..3
    __shared__ int    s_sp[NSWEEP][12];        // per sweep: v1, v2, bas[0..9]
    __shared__ float  s_ez[NC];

    const int b = blockIdx.x;
    const int tid = threadIdx.x;

    // ---- phase A: init state, GF(2) ring matrices, fused gate matrices ----
    for (int i = tid; i < DIM; i += TPB)
        st[i] = make_float2(i == 0 ? 1.0f : 0.0f, 0.0f);   // sw(0)==0
    if (tid < NC) s_ez[tid] = 0.0f;

    if (tid == 0) {
        // ring map M (amplitude perm C|i> = |M i>), built in application order
        int M[NQ], Mi[NQ];
        for (int r = 0; r < NQ; r++) { M[r] = 1 << r; Mi[r] = 1 << r; }
        for (int q = 0; q < NQ; q++) {           // CNOT(q, q+1), q ascending
            int pc = NQ - 1 - q, pt = NQ - 1 - ((q + 1) % NQ);
            M[pt] ^= M[pc];
        }
        for (int q = NQ - 1; q >= 0; q--) {      // inverse: reversed order
            int pc = NQ - 1 - q, pt = NQ - 1 - ((q + 1) % NQ);
            Mi[pt] ^= Mi[pc];
        }
        // powers M^l and M^{-l}
        int P[NQ], Pi[NQ];
        for (int r = 0; r < NQ; r++) { P[r] = 1 << r; Pi[r] = 1 << r; }
        for (int l = 0; l <= NL; l++) {
            for (int r = 0; r < NQ; r++) s_Mp[l][r] = P[r];
            if (l < NL) for (int r = 0; r < NQ; r++) s_Mip[l][r] = Pi[r];
            int Pn[NQ], Pin[NQ];
            for (int r = 0; r < NQ; r++) {
                int acc = 0, acci = 0;
                for (int s = 0; s < NQ; s++) {
                    if ((M[r]  >> s) & 1) acc  ^= P[s];
                    if ((Mi[r] >> s) & 1) acci ^= Pi[s];
                }
                Pn[r] = acc; Pin[r] = acci;
            }
            for (int r = 0; r < NQ; r++) { P[r] = Pn[r]; Pi[r] = Pin[r]; }
        }
    }

    if (tid < NL * NQ) {   // fused gate U = Rot(w) @ RY(x); store alpha=U00, beta=U01
        const int l = tid / NQ, q = tid % NQ;
        const float xh = 0.5f * x[b * NQ + q];
        float sy, cy; sincosf(xh, &sy, &cy);
        const float phi = w[(l * NQ + q) * 3 + 0];
        const float th  = w[(l * NQ + q) * 3 + 1];
        const float om  = w[(l * NQ + q) * 3 + 2];
        float stt, ct; sincosf(0.5f * th, &stt, &ct);
        const float a1 = -0.5f * (phi + om);
        const float a2 =  0.5f * (phi - om);
        float s1, c1, s2, c2;
        sincosf(a1, &s1, &c1);
        sincosf(a2, &s2, &c2);
        const float R00r =  c1 * ct, R00i =  s1 * ct;
        const float R01r = -c2 * stt, R01i = -s2 * stt;
        s_g[tid][0] = make_float2( R00r * cy + R01r * sy,  R00i * cy + R01i * sy);
        s_g[tid][1] = make_float2(-R00r * sy + R01r * cy, -R00i * sy + R01i * cy);
    }
    __syncthreads();

    // ---- phase B: per-sweep params (masks + bank-aware null-space basis) ----
    if (tid < NSWEEP) {
        const int l = tid / 6, k = tid % 6;
        const int pa = NQ - 1 - 2 * k;           // bit of qubit 2k
        const int pb = NQ - 1 - (2 * k + 1);     // bit of qubit 2k+1
        int v1 = 0, v2 = 0;                      // columns of M^{-l}
        for (int r = 0; r < NQ; r++) {
            v1 |= ((s_Mip[l][r] >> pa) & 1) << r;
            v2 |= ((s_Mip[l][r] >> pb) & 1) << r;
        }
        int D1 = s_Mp[l][pa], D2 = s_Mp[l][pb];  // duals: rows of M^l
        const int p1 = __ffs(D1) - 1;
        if ((D2 >> p1) & 1) D2 ^= D1;
        const int p2 = __ffs(D2) - 1;
        if ((D1 >> p2) & 1) D1 ^= D2;
        s_sp[tid][0] = v1;
        s_sp[tid][1] = v2;

        int bas[10];
        int freeb = 0xFFF & ~((1 << p1) | (1 << p2));
        for (int jj = 0; jj < 10; jj++) {
            const int j = __ffs(freeb) - 1; freeb &= freeb - 1;
            bas[jj] = (1 << j) ^ (((D1 >> j) & 1) << p1)
                               ^ (((D2 >> j) & 1) << p2);
        }
        // Reorder: slots 0..3 (warp lane bits 0..3) get vectors whose swizzled
        // low nibbles are GF(2)-independent -> every 16-lane phase of LDS.64/
        // STS.64 hits 16 distinct bank pairs (conflict-free).
        int out[10];
        int ech[4]; int necc = 0;
        int nsel = 0, ntail = 9;
        for (int i = 0; i < 10; i++) {
            int r = sw(bas[i]) & 15;
            for (int j = 0; j < necc; j++) {
                const int rx = r ^ ech[j];
                r = rx < r ? rx : r;
            }
            if (r != 0 && nsel < 4) { ech[necc++] = r; out[nsel++] = bas[i]; }
            else out[ntail--] = bas[i];
        }
        for (int jj = 0; jj < 10; jj++) s_sp[tid][2 + jj] = out[jj];
    }
    __syncthreads();

    u64* st64 = reinterpret_cast<u64*>(st);

    // ---- phase C: 24 two-qubit sweeps (CNOT rings folded into masks) ----
    for (int swp = 0; swp < NSWEEP; swp++) {
        const int l = swp / 6, k = swp % 6;
        // swizzled pair/quad offsets (sw is XOR-linear)
        const int sv1  = sw(s_sp[swp][0]);
        const int sv2  = sw(s_sp[swp][1]);
        const int sv12 = sv1 ^ sv2;
        const int sb8  = sw(s_sp[swp][10]);
        const int sb9  = sw(s_sp[swp][11]);

        // swizzled base slot for this thread
        int i0b = 0;
#pragma unroll
        for (int jj = 0; jj < 8; jj++)
            i0b ^= ((tid >> jj) & 1) ? s_sp[swp][2 + jj] : 0;
        const int base = sw(i0b);

        const PG Ga = mkpg(s_g[l * NQ + 2 * k][0],     s_g[l * NQ + 2 * k][1]);
        const PG Gb = mkpg(s_g[l * NQ + 2 * k + 1][0], s_g[l * NQ + 2 * k + 1][1]);

#pragma unroll 2
        for (int u = 0; u < QUADS / TPB; u++) {
            const int j00 = base ^ ((u & 1) ? sb8 : 0) ^ ((u & 2) ? sb9 : 0);
            const int j01 = j00 ^ sv2;
            const int j10 = j00 ^ sv1;
            const int j11 = j00 ^ sv12;
            u64 s00 = st64[j00], s01 = st64[j01], s10 = st64[j10], s11 = st64[j11];
            pgate(Gb, s00, s01);   // U_b on qubit 2k+1
            pgate(Gb, s10, s11);
            pgate(Ga, s00, s10);   // U_a on qubit 2k
            pgate(Ga, s01, s11);
            st64[j00] = s00; st64[j01] = s01; st64[j10] = s10; st64[j11] = s11;
        }
        __syncthreads();
    }

    // ---- measurement: <Z_c>, final C^4 folded in; iterate slots directly ----
    // parity(i & d) with i = sw^{-1}(s)  ==  parity(s & d~), d~ = (d^d<<4^d<<8)&0xFFF
    int dz[NC];
#pragma unroll
    for (int c = 0; c < NC; c++) {
        const int d = s_Mp[NL][NQ - 1 - c];
        dz[c] = (d ^ (d << 4) ^ (d << 8)) & 0xFFF;
    }

    float ez[NC];
#pragma unroll
    for (int c = 0; c < NC; c++) ez[c] = 0.0f;
    for (int s = tid; s < DIM; s += TPB) {
        const float2 a = st[s];
        const float p = a.x * a.x + a.y * a.y;
#pragma unroll
        for (int c = 0; c < NC; c++)
            ez[c] += (__popc(s & dz[c]) & 1) ? -p : p;
    }
#pragma unroll
    for (int c = 0; c < NC; c++) {
        float v = ez[c];
        for (int o = 16; o > 0; o >>= 1) v += __shfl_down_sync(0xffffffffu, v, o);
        if ((tid & 31) == 0) atomicAdd(&s_ez[c], v);
    }
    __syncthreads();

    // ---- softmax(expz + bias) -> g_probs ----
    if (tid == 0) {
        float z[NC];
        float m = -1e30f;
#pragma unroll
        for (int c = 0; c < NC; c++) {
            z[c] = s_ez[c] + bias[c];
            m = fmaxf(m, z[c]);
        }
        float sum = 0.0f;
#pragma unroll
        for (int c = 0; c < NC; c++) {
            z[c] = expf(z[c] - m);
            sum += z[c];
        }
        const float inv = 1.0f / sum;
#pragma unroll
        for (int c = 0; c < NC; c++) g_probs[b * NC + c] = z[c] * inv;
    }
}

// BatchNorm1d over the batch, per class. 10 blocks x 512 threads.
__global__ __launch_bounds__(BATCH) void bn_kernel(const float* __restrict__ gamma,
                                                   const float* __restrict__ beta,
                                                   float* __restrict__ out) {
    const int c = blockIdx.x;
    const int t = threadIdx.x;  // = batch index

    const float p = g_probs[t * NC + c];

    __shared__ float ssum[BATCH / 32];
    __shared__ float ssq[BATCH / 32];
    float s = p, q = p * p;
    for (int o = 16; o > 0; o >>= 1) {
        s += __shfl_down_sync(0xffffffffu, s, o);
        q += __shfl_down_sync(0xffffffffu, q, o);
    }
    if ((t & 31) == 0) {
        ssum[t >> 5] = s;
        ssq[t >> 5] = q;
    }
    __syncthreads();

    __shared__ float smu, srstd;
    if (t == 0) {
        float S = 0.0f, Q = 0.0f;
#pragma unroll
        for (int i = 0; i < BATCH / 32; i++) { S += ssum[i]; Q += ssq[i]; }
        const float mu = S / (float)BATCH;
        const float var = Q / (float)BATCH - mu * mu;
        smu = mu;
        srstd = rsqrtf(var + BN_EPS);
    }
    __syncthreads();

    out[t * NC + c] = (p - smu) * srstd * gamma[c] + beta[c];
}

extern "C" void kernel_launch(void* const* d_in, const int* in_sizes, int n_in,
                              void* d_out, int out_size) {
    const float* x      = (const float*)d_in[0];  // (512, 12)
    const float* wts    = (const float*)d_in[1];  // (4, 12, 3)
    const float* bias   = (const float*)d_in[2];  // (10,)
    const float* gamma  = (const float*)d_in[3];  // (10,)
    const float* beta   = (const float*)d_in[4];  // (10,)
    float* out = (float*)d_out;                   // (512, 10)

    vqc_kernel<<<BATCH, TPB>>>(x, wts, bias);
    bn_kernel<<<NC, BATCH>>>(gamma, beta, out);
}

// round 7
// speedup vs baseline: 1.1645x; 1.0832x over previous
#include <cuda_runtime.h>
#include <math.h>

#define NQ 12
#define DIM 4096
#define QUADS 1024
#define NL 4
#define NC 10
#define BATCH 512
#define TPB 256
#define BN_EPS 1e-5f
#define NSWEEP (NL * NQ / 2)   // 24

typedef unsigned long long u64;

// Scratch for softmax probs (B x NC) + completion counter. Allocation-free.
__device__ float g_probs[BATCH * NC];
__device__ unsigned g_cnt = 0;

// ---------------- compile-time GF(2) circuit tables ----------------
// storage swizzle: amplitude i lives at slot i ^ (i>>4) (bijective, XOR-linear)
constexpr int csw(int i) { return i ^ (i >> 4); }
constexpr int cctz(int v) { int n = 0; while (!(v & 1)) { v >>= 1; n++; } return n; }

struct Tab {
    int sp[NSWEEP][12];   // per sweep: sw(v1), sw(v2), sw(bas[0..9]) bank-ordered
    int dz[NC];           // swizzled parity masks for <Z_c> with C^4 folded in
};

constexpr Tab make_tab() {
    Tab t{};
    // ring map M (amplitude perm C|i> = |M i>), built in application order
    int M[NQ] = {}, Mi[NQ] = {};
    for (int r = 0; r < NQ; r++) { M[r] = 1 << r; Mi[r] = 1 << r; }
    for (int q = 0; q < NQ; q++) {             // CNOT(q, q+1), q ascending
        int pc = NQ - 1 - q, pt = NQ - 1 - ((q + 1) % NQ);
        M[pt] ^= M[pc];
    }
    for (int q = NQ - 1; q >= 0; q--) {        // inverse: reversed order
        int pc = NQ - 1 - q, pt = NQ - 1 - ((q + 1) % NQ);
        Mi[pt] ^= Mi[pc];
    }
    // powers M^l (l=0..4) and M^{-l} (l=0..3)
    int Mp[NL + 1][NQ] = {}, Mip[NL][NQ] = {};
    int P[NQ] = {}, Pi_[NQ] = {};
    for (int r = 0; r < NQ; r++) { P[r] = 1 << r; Pi_[r] = 1 << r; }
    for (int l = 0; l <= NL; l++) {
        for (int r = 0; r < NQ; r++) Mp[l][r] = P[r];
        if (l < NL) for (int r = 0; r < NQ; r++) Mip[l][r] = Pi_[r];
        int Pn[NQ] = {}, Pin[NQ] = {};
        for (int r = 0; r < NQ; r++) {
            int acc = 0, acci = 0;
            for (int s = 0; s < NQ; s++) {
                if ((M[r]  >> s) & 1) acc  ^= P[s];
                if ((Mi[r] >> s) & 1) acci ^= Pi_[s];
            }
            Pn[r] = acc; Pin[r] = acci;
        }
        for (int r = 0; r < NQ; r++) { P[r] = Pn[r]; Pi_[r] = Pin[r]; }
    }
    // per-sweep masks + bank-aware null-space basis
    for (int idx = 0; idx < NSWEEP; idx++) {
        int l = idx / 6, k = idx % 6;
        int pa = NQ - 1 - 2 * k;               // bit of qubit 2k
        int pb = NQ - 1 - (2 * k + 1);         // bit of qubit 2k+1
        int v1 = 0, v2 = 0;                    // columns of M^{-l}
        for (int r = 0; r < NQ; r++) {
            v1 |= ((Mip[l][r] >> pa) & 1) << r;
            v2 |= ((Mip[l][r] >> pb) & 1) << r;
        }
        int D1 = Mp[l][pa], D2 = Mp[l][pb];    // duals: rows of M^l
        int p1 = cctz(D1);
        if ((D2 >> p1) & 1) D2 ^= D1;
        int p2 = cctz(D2);
        if ((D1 >> p2) & 1) D1 ^= D2;
        t.sp[idx][0] = csw(v1);
        t.sp[idx][1] = csw(v2);
        int bas[10] = {};
        int freeb = 0xFFF & ~((1 << p1) | (1 << p2));
        for (int jj = 0; jj < 10; jj++) {
            int j = cctz(freeb); freeb &= freeb - 1;
            bas[jj] = (1 << j) ^ (((D1 >> j) & 1) << p1)
                               ^ (((D2 >> j) & 1) << p2);
        }
        // slots 0..3 (lane bits 0..3) get vectors with GF(2)-independent
        // swizzled low nibbles -> conflict-free LDS.64/STS.64 phases
        int out[10] = {}; int ech[4] = {}; int necc = 0, nsel = 0, ntail = 9;
        for (int i = 0; i < 10; i++) {
            int r = csw(bas[i]) & 15;
            for (int j = 0; j < necc; j++) { int rx = r ^ ech[j]; r = rx < r ? rx : r; }
            if (r != 0 && nsel < 4) { ech[necc++] = r; out[nsel++] = bas[i]; }
            else out[ntail--] = bas[i];
        }
        for (int jj = 0; jj < 10; jj++) t.sp[idx][2 + jj] = csw(out[jj]);
    }
    // measurement parity masks, pre-transformed by sw^T
    for (int c = 0; c < NC; c++) {
        int d = Mp[NL][NQ - 1 - c];
        t.dz[c] = (d ^ (d << 4) ^ (d << 8)) & 0xFFF;
    }
    return t;
}

__constant__ Tab c_tab = make_tab();

// ---------------- packed f32x2 helpers ----------------
__device__ __forceinline__ u64 swap64(u64 v) {  // (x,y) -> (y,x)
    u64 r;
    asm("{\n\t.reg .b32 x, y;\n\tmov.b64 {x, y}, %1;\n\tmov.b64 %0, {y, x};\n\t}"
        : "=l"(r) : "l"(v));
    return r;
}
__device__ __forceinline__ u64 fma2(u64 a, u64 b, u64 c) {
    u64 d; asm("fma.rn.f32x2 %0, %1, %2, %3;" : "=l"(d) : "l"(a), "l"(b), "l"(c));
    return d;
}
__device__ __forceinline__ u64 mul2(u64 a, u64 b) {
    u64 d; asm("mul.rn.f32x2 %0, %1, %2;" : "=l"(d) : "l"(a), "l"(b));
    return d;
}
__device__ __forceinline__ u64 pack2(float lo, float hi) {
    u64 d; asm("mov.b64 %0, {%1, %2};" : "=l"(d) : "f"(lo), "f"(hi));
    return d;
}

// packed SU(2) gate: U = [[a, b], [-b*, a*]], 6 broadcast/sign-prepped f32x2 consts
struct PG { u64 axx, ayn, ayc, bxx, bxn, byn; };

__device__ __forceinline__ PG mkpg(float2 al, float2 be) {
    PG g;
    g.axx = pack2(al.x, al.x);
    g.ayn = pack2(-al.y, al.y);
    g.ayc = pack2(al.y, -al.y);
    g.bxx = pack2(be.x, be.x);
    g.bxn = pack2(-be.x, -be.x);
    g.byn = pack2(-be.y, be.y);
    return g;
}

// (a,b) <- U (a,b), amplitudes packed as (re,im) f32x2
__device__ __forceinline__ void pgate(const PG& g, u64& a, u64& b) {
    const u64 as = swap64(a), bs = swap64(b);
    u64 t = mul2(g.byn, bs);          // na = alpha*a + beta*b
    t = fma2(g.bxx, b, t);
    t = fma2(g.ayn, as, t);
    t = fma2(g.axx, a, t);
    u64 u = mul2(g.ayc, bs);          // nb = -conj(beta)*a + conj(alpha)*b
    u = fma2(g.axx, b, u);
    u = fma2(g.byn, as, u);
    u = fma2(g.bxn, a, u);
    a = t; b = u;
}

__global__ __launch_bounds__(TPB, 4) void vqc_kernel(const float* __restrict__ x,
                                                     const float* __restrict__ w,
                                                     const float* __restrict__ bias,
                                                     const float* __restrict__ gamma,
                                                     const float* __restrict__ beta,
                                                     float* __restrict__ out) {
    __shared__ float2 st[DIM];                 // state, swizzled slots
    __shared__ float2 s_g[NL * NQ][2];         // fused RY*Rot gate: (U00, U01)
    __shared__ float  s_ez[NC];
    __shared__ unsigned s_last;

    const int b = blockIdx.x;
    const int tid = threadIdx.x;

    // ---- init state + fused gate matrices ----
    for (int i = tid; i < DIM; i += TPB)
        st[i] = make_float2(i == 0 ? 1.0f : 0.0f, 0.0f);   // sw(0)==0
    if (tid < NC) s_ez[tid] = 0.0f;

    if (tid < NL * NQ) {   // fused gate U = Rot(w) @ RY(x); store alpha=U00, beta=U01
        const int l = tid / NQ, q = tid % NQ;
        const float xh = 0.5f * x[b * NQ + q];
        float sy, cy; sincosf(xh, &sy, &cy);
        const float phi = w[(l * NQ + q) * 3 + 0];
        const float th  = w[(l * NQ + q) * 3 + 1];
        const float om  = w[(l * NQ + q) * 3 + 2];
        float stt, ct; sincosf(0.5f * th, &stt, &ct);
        const float a1 = -0.5f * (phi + om);
        const float a2 =  0.5f * (phi - om);
        float s1, c1, s2, c2;
        sincosf(a1, &s1, &c1);
        sincosf(a2, &s2, &c2);
        const float R00r =  c1 * ct, R00i =  s1 * ct;
        const float R01r = -c2 * stt, R01i = -s2 * stt;
        s_g[tid][0] = make_float2( R00r * cy + R01r * sy,  R00i * cy + R01i * sy);
        s_g[tid][1] = make_float2(-R00r * sy + R01r * cy, -R00i * sy + R01i * cy);
    }
    __syncthreads();

    u64* st64 = reinterpret_cast<u64*>(st);

    // ---- 24 two-qubit sweeps (CNOT rings folded into masks) ----
    for (int swp = 0; swp < NSWEEP; swp++) {
        const int l = swp / 6, k = swp % 6;
        const int sv1  = c_tab.sp[swp][0];
        const int sv2  = c_tab.sp[swp][1];
        const int sv12 = sv1 ^ sv2;
        const int sb8  = c_tab.sp[swp][10];
        const int sb9  = c_tab.sp[swp][11];

        // swizzled base slot for this thread (basis pre-swizzled; sw is linear)
        int base = 0;
#pragma unroll
        for (int jj = 0; jj < 8; jj++)
            base ^= ((tid >> jj) & 1) ? c_tab.sp[swp][2 + jj] : 0;

        const PG Ga = mkpg(s_g[l * NQ + 2 * k][0],     s_g[l * NQ + 2 * k][1]);
        const PG Gb = mkpg(s_g[l * NQ + 2 * k + 1][0], s_g[l * NQ + 2 * k + 1][1]);

#pragma unroll 2
        for (int u = 0; u < QUADS / TPB; u++) {
            const int j00 = base ^ ((u & 1) ? sb8 : 0) ^ ((u & 2) ? sb9 : 0);
            const int j01 = j00 ^ sv2;
            const int j10 = j00 ^ sv1;
            const int j11 = j00 ^ sv12;
            u64 s00 = st64[j00], s01 = st64[j01], s10 = st64[j10], s11 = st64[j11];
            pgate(Gb, s00, s01);   // U_b on qubit 2k+1
            pgate(Gb, s10, s11);
            pgate(Ga, s00, s10);   // U_a on qubit 2k
            pgate(Ga, s01, s11);
            st64[j00] = s00; st64[j01] = s01; st64[j10] = s10; st64[j11] = s11;
        }
        __syncthreads();
    }

    // ---- measurement: <Z_c>, final C^4 folded in; iterate slots directly ----
    float ez[NC];
#pragma unroll
    for (int c = 0; c < NC; c++) ez[c] = 0.0f;
    for (int s = tid; s < DIM; s += TPB) {
        const float2 a = st[s];
        const float p = a.x * a.x + a.y * a.y;
#pragma unroll
        for (int c = 0; c < NC; c++)
            ez[c] += (__popc(s & c_tab.dz[c]) & 1) ? -p : p;
    }
#pragma unroll
    for (int c = 0; c < NC; c++) {
        float v = ez[c];
        for (int o = 16; o > 0; o >>= 1) v += __shfl_down_sync(0xffffffffu, v, o);
        if ((tid & 31) == 0) atomicAdd(&s_ez[c], v);
    }
    __syncthreads();

    // ---- softmax(expz + bias) -> g_probs; take completion ticket ----
    if (tid == 0) {
        float z[NC];
        float m = -1e30f;
#pragma unroll
        for (int c = 0; c < NC; c++) {
            z[c] = s_ez[c] + bias[c];
            m = fmaxf(m, z[c]);
        }
        float sum = 0.0f;
#pragma unroll
        for (int c = 0; c < NC; c++) {
            z[c] = expf(z[c] - m);
            sum += z[c];
        }
        const float inv = 1.0f / sum;
#pragma unroll
        for (int c = 0; c < NC; c++) g_probs[b * NC + c] = z[c] * inv;
        __threadfence();
        s_last = atomicAdd(&g_cnt, 1u);
    }
    __syncthreads();

    // ---- BN epilogue: performed entirely by the last-arriving block ----
    if (s_last == BATCH - 1u) {
        if (tid == 0) g_cnt = 0;          // reset for next (graph-replayed) call
        __threadfence();                  // make all blocks' g_probs reads fresh

        __shared__ float smu[NC], srs[NC];
        const int wid = tid >> 5, lid = tid & 31;
        for (int c = wid; c < NC; c += TPB / 32) {
            float s = 0.0f, q = 0.0f;
            for (int t2 = lid; t2 < BATCH; t2 += 32) {
                const float p = g_probs[t2 * NC + c];
                s += p; q += p * p;
            }
            for (int o = 16; o > 0; o >>= 1) {
                s += __shfl_down_sync(0xffffffffu, s, o);
                q += __shfl_down_sync(0xffffffffu, q, o);
            }
            if (lid == 0) {
                const float mu = s / (float)BATCH;
                smu[c] = mu;
                srs[c] = rsqrtf(q / (float)BATCH - mu * mu + BN_EPS);
            }
        }
        __syncthreads();
        for (int i = tid; i < BATCH * NC; i += TPB) {
            const int c = i % NC;
            out[i] = (g_probs[i] - smu[c]) * srs[c] * gamma[c] + beta[c];
        }
    }
}

extern "C" void kernel_launch(void* const* d_in, const int* in_sizes, int n_in,
                              void* d_out, int out_size) {
    const float* x      = (const float*)d_in[0];  // (512, 12)
    const float* wts    = (const float*)d_in[1];  // (4, 12, 3)
    const float* bias   = (const float*)d_in[2];  // (10,)
    const float* gamma  = (const float*)d_in[3];  // (10,)
    const float* beta   = (const float*)d_in[4];  // (10,)
    float* out = (float*)d_out;                   // (512, 10)

    vqc_kernel<<<BATCH, TPB>>>(x, wts, bias, gamma, beta, out);
}